// round 4
// baseline (speedup 1.0000x reference)
#include <cuda_runtime.h>
#include <math.h>

#define B_    64
#define T_    2048
#define ENC_  512
#define DEC_  1024
#define CONV_ 32
#define KW_   31
#define HID_  256
#define PAD_  15
#define NSPLIT_ 8

// -------- scratch (static device globals; no allocation) --------
static __device__ float g_convp[(size_t)B_ * T_ * CONV_];   // (B,T,CONV) 16 MB
static __device__ float g_decp[B_ * HID_];                  // dec proj + b_enc
static __device__ float g_energy[B_ * T_];
static __device__ float g_part[B_ * NSPLIT_ * ENC_];        // att_c partials

// ---- packed f32x2 helpers (Blackwell packed-fp32 pipe) ----
__device__ __forceinline__ void ffma2(unsigned long long& d,
                                      unsigned long long a,
                                      unsigned long long b) {
    asm("fma.rn.f32x2 %0, %1, %2, %3;" : "=l"(d) : "l"(a), "l"(b), "l"(d));
}
__device__ __forceinline__ unsigned long long pack2(float lo, float hi) {
    unsigned long long r;
    asm("mov.b64 %0, {%1, %2};" : "=l"(r) : "f"(lo), "f"(hi));
    return r;
}
__device__ __forceinline__ void unpack2(float& lo, float& hi, unsigned long long v) {
    asm("mov.b64 {%0, %1}, %2;" : "=f"(lo), "=f"(hi) : "l"(v));
}

// ================= K0: dec_proj[b,h] = dec_state[b,:] @ W_dec[h,:] + b_enc[h]
__global__ void k_decproj(const float* __restrict__ dec_state,
                          const float* __restrict__ W_dec,
                          const float* __restrict__ b_enc) {
    __shared__ float sdec[DEC_];
    int b = blockIdx.x;
    int tid = threadIdx.x;
    for (int i = tid; i < DEC_; i += 256) sdec[i] = dec_state[b * DEC_ + i];
    __syncthreads();
    int h = tid;  // 256 threads == HID
    const float* wr = W_dec + (size_t)h * DEC_;
    float acc = b_enc[h];
#pragma unroll 4
    for (int d = 0; d < DEC_; d += 4) {
        float4 w4 = *(const float4*)(wr + d);
        acc += sdec[d] * w4.x + sdec[d + 1] * w4.y + sdec[d + 2] * w4.z + sdec[d + 3] * w4.w;
    }
    g_decp[b * HID_ + h] = acc;
}

// ================= K1: location conv
__global__ void k_conv(const float* __restrict__ prev,
                       const float* __restrict__ cw) {
    __shared__ float sprev[128 + KW_ - 1];
    __shared__ float scw[CONV_ * KW_];
    int b = blockIdx.y;
    int t0 = blockIdx.x * 128;
    int tid = threadIdx.x;  // 128
    for (int i = tid; i < 128 + KW_ - 1; i += 128) {
        int g = t0 - PAD_ + i;
        sprev[i] = (g >= 0 && g < T_) ? prev[b * T_ + g] : 0.0f;
    }
    for (int i = tid; i < CONV_ * KW_; i += 128) scw[i] = cw[i];
    __syncthreads();
    float* outp = g_convp + ((size_t)(b * T_ + t0 + tid)) * CONV_;
#pragma unroll 4
    for (int c = 0; c < CONV_; c++) {
        float acc = 0.0f;
        const float* w = scw + c * KW_;
#pragma unroll
        for (int k = 0; k < KW_; k++) acc += sprev[tid + k] * w[k];
        outp[c] = acc;
    }
}

// ================= K2: fused energy GEMM (f32x2 packed, double-buffered) ====
// energy[b,t] = w_b + sum_h w_w[h]*tanh(enc@W_enc^T + convp@W_att^T + decp)
#define APAD 68
#define BPAD 260
#define NCHUNK 34   // 32 ENC chunks + 2 CONV chunks

__global__ __launch_bounds__(256, 2)
void k_energy(const float* __restrict__ enc,
              const float* __restrict__ W_enc,
              const float* __restrict__ W_att,
              const float* __restrict__ w_w,
              const float* __restrict__ w_b) {
    // k-major tiles, double-buffered
    __shared__ float sA[2][16][APAD];   // [buf][k][row 0..63]
    __shared__ float sB[2][16][BPAD];   // [buf][k][col 0..255]

    int tile = blockIdx.x;          // 2048 tiles
    int b = tile >> 5;
    int t0 = (tile & 31) << 6;      // *64
    int tid = threadIdx.x;
    int cx = tid & 15;              // col group: 16 consecutive cols
    int ry = tid >> 4;              // row group: 4 consecutive rows
    int c0 = cx << 4;
    int r0 = ry << 2;

    // loader indices
    const int row_ld = tid >> 2;          // 0..63
    const int kq_ld = (tid & 3) * 4;      // 0,4,8,12
    const float* enc_row = enc + ((size_t)(b * T_ + t0 + row_ld)) * ENC_ + kq_ld;
    const float* conv_row = g_convp + ((size_t)(b * T_ + t0 + row_ld)) * CONV_ + kq_ld;
    const float* wenc_row = W_enc + (size_t)tid * ENC_;
    const float* watt_row = W_att + (size_t)tid * CONV_;

    unsigned long long acc[4][8];
#pragma unroll
    for (int i = 0; i < 4; i++)
#pragma unroll
        for (int j = 0; j < 8; j++) acc[i][j] = 0ull;

    // ---- chunk loader (it in [0, NCHUNK)) ----
    auto load_chunk = [&](int it, int buf) {
        float4 av;
        if (it < 32) {
            av = *(const float4*)(enc_row + it * 16);
        } else {
            av = *(const float4*)(conv_row + (it - 32) * 16);
        }
        sA[buf][kq_ld + 0][row_ld] = av.x;
        sA[buf][kq_ld + 1][row_ld] = av.y;
        sA[buf][kq_ld + 2][row_ld] = av.z;
        sA[buf][kq_ld + 3][row_ld] = av.w;
        if (it < 32) {
#pragma unroll
            for (int q = 0; q < 4; q++) {
                float4 wv = *(const float4*)(wenc_row + it * 16 + q * 4);
                sB[buf][q * 4 + 0][tid] = wv.x;
                sB[buf][q * 4 + 1][tid] = wv.y;
                sB[buf][q * 4 + 2][tid] = wv.z;
                sB[buf][q * 4 + 3][tid] = wv.w;
            }
        } else {
#pragma unroll
            for (int q = 0; q < 4; q++) {
                float4 wv = *(const float4*)(watt_row + (it - 32) * 16 + q * 4);
                sB[buf][q * 4 + 0][tid] = wv.x;
                sB[buf][q * 4 + 1][tid] = wv.y;
                sB[buf][q * 4 + 2][tid] = wv.z;
                sB[buf][q * 4 + 3][tid] = wv.w;
            }
        }
    };

    load_chunk(0, 0);
    __syncthreads();

    for (int it = 0; it < NCHUNK; it++) {
        int buf = it & 1;
        if (it + 1 < NCHUNK) load_chunk(it + 1, buf ^ 1);
#pragma unroll
        for (int k = 0; k < 16; k++) {
            float4 av = *(const float4*)&sA[buf][k][r0];
            unsigned long long ap0 = pack2(av.x, av.x);
            unsigned long long ap1 = pack2(av.y, av.y);
            unsigned long long ap2 = pack2(av.z, av.z);
            unsigned long long ap3 = pack2(av.w, av.w);
            unsigned long long bp[8];
#pragma unroll
            for (int q = 0; q < 4; q++) {
                float4 bv = *(const float4*)&sB[buf][k][c0 + q * 4];
                bp[q * 2 + 0] = pack2(bv.x, bv.y);
                bp[q * 2 + 1] = pack2(bv.z, bv.w);
            }
#pragma unroll
            for (int j = 0; j < 8; j++) {
                ffma2(acc[0][j], ap0, bp[j]);
                ffma2(acc[1][j], ap1, bp[j]);
                ffma2(acc[2][j], ap2, bp[j]);
                ffma2(acc[3][j], ap3, bp[j]);
            }
        }
        __syncthreads();
    }

    // ---- epilogue: + dec, tanh, dot with w_w, 16-lane reduce per row ----
    float decv[16], wv[16];
#pragma unroll
    for (int q = 0; q < 4; q++) {
        float4 dv = *(const float4*)(g_decp + b * HID_ + c0 + q * 4);
        float4 ww = *(const float4*)(w_w + c0 + q * 4);
        decv[q * 4 + 0] = dv.x; decv[q * 4 + 1] = dv.y;
        decv[q * 4 + 2] = dv.z; decv[q * 4 + 3] = dv.w;
        wv[q * 4 + 0] = ww.x; wv[q * 4 + 1] = ww.y;
        wv[q * 4 + 2] = ww.z; wv[q * 4 + 3] = ww.w;
    }
    float wb = w_b[0];
#pragma unroll
    for (int i = 0; i < 4; i++) {
        float e = 0.0f;
#pragma unroll
        for (int j = 0; j < 8; j++) {
            float lo, hi;
            unpack2(lo, hi, acc[i][j]);
            e += wv[2 * j + 0] * tanhf(lo + decv[2 * j + 0]);
            e += wv[2 * j + 1] * tanhf(hi + decv[2 * j + 1]);
        }
        // reduce across 16 cx lanes (contiguous 16-lane group inside a warp)
        e += __shfl_xor_sync(0xffffffffu, e, 8);
        e += __shfl_xor_sync(0xffffffffu, e, 4);
        e += __shfl_xor_sync(0xffffffffu, e, 2);
        e += __shfl_xor_sync(0xffffffffu, e, 1);
        if (cx == 0) g_energy[b * T_ + t0 + r0 + i] = e + wb;
    }
}

// ================= K3: masked softmax over T per batch row -> att_w into out
__global__ void k_softmax(const int* __restrict__ text_len,
                          float* __restrict__ out_attw) {
    __shared__ float sred[32];
    int b = blockIdx.x;
    int tid = threadIdx.x;  // 256
    int len = text_len[b];
    float vals[8];
    float m = -INFINITY;
#pragma unroll
    for (int p = 0; p < 8; p++) {
        int t = tid + 256 * p;
        float e = g_energy[b * T_ + t];
        vals[p] = e;
        if (t < len) m = fmaxf(m, e);
    }
    for (int o = 16; o > 0; o >>= 1) m = fmaxf(m, __shfl_xor_sync(0xffffffffu, m, o));
    if ((tid & 31) == 0) sred[tid >> 5] = m;
    __syncthreads();
    if (tid < 32) {
        float v = (tid < 8) ? sred[tid] : -INFINITY;
        for (int o = 4; o > 0; o >>= 1) v = fmaxf(v, __shfl_xor_sync(0xffffffffu, v, o));
        if (tid == 0) sred[0] = v;
    }
    __syncthreads();
    m = sred[0];
    __syncthreads();

    float s = 0.0f;
#pragma unroll
    for (int p = 0; p < 8; p++) {
        int t = tid + 256 * p;
        float v = (t < len) ? expf(vals[p] - m) : 0.0f;
        vals[p] = v;
        s += v;
    }
    for (int o = 16; o > 0; o >>= 1) s += __shfl_xor_sync(0xffffffffu, s, o);
    if ((tid & 31) == 0) sred[tid >> 5] = s;
    __syncthreads();
    if (tid < 32) {
        float v = (tid < 8) ? sred[tid] : 0.0f;
        for (int o = 4; o > 0; o >>= 1) v += __shfl_xor_sync(0xffffffffu, v, o);
        if (tid == 0) sred[0] = v;
    }
    __syncthreads();
    float inv = 1.0f / sred[0];
#pragma unroll
    for (int p = 0; p < 8; p++) {
        int t = tid + 256 * p;
        out_attw[b * T_ + t] = vals[p] * inv;
    }
}

// ================= K4: att_c partials: split T into NSPLIT chunks
__global__ void k_attc_part(const float* __restrict__ enc,
                            const float* __restrict__ attw) {
    __shared__ float sw[256];
    int b = blockIdx.z;
    int split = blockIdx.y;
    int c = blockIdx.x * 256 + threadIdx.x;
    int t0 = split * 256;
    sw[threadIdx.x] = attw[b * T_ + t0 + threadIdx.x];
    __syncthreads();
    const float* base = enc + ((size_t)(b * T_ + t0)) * ENC_ + c;
    float acc = 0.0f;
#pragma unroll 4
    for (int t = 0; t < 256; t++) acc += base[(size_t)t * ENC_] * sw[t];
    g_part[(b * NSPLIT_ + split) * ENC_ + c] = acc;
}

// ================= K5: reduce partials -> att_c
__global__ void k_attc_reduce(float* __restrict__ out_attc) {
    int idx = blockIdx.x * 256 + threadIdx.x;
    int b = idx / ENC_;
    int c = idx % ENC_;
    float s = 0.0f;
#pragma unroll
    for (int p = 0; p < NSPLIT_; p++) s += g_part[(b * NSPLIT_ + p) * ENC_ + c];
    out_attc[idx] = s;
}

// ================= launcher =================
extern "C" void kernel_launch(void* const* d_in, const int* in_sizes, int n_in,
                              void* d_out, int out_size) {
    const float* enc      = (const float*)d_in[0];
    const float* dec_st   = (const float*)d_in[1];
    const float* prev     = (const float*)d_in[2];
    const int*   text_len = (const int*)  d_in[3];
    const float* W_enc    = (const float*)d_in[4];
    const float* b_enc    = (const float*)d_in[5];
    const float* W_dec    = (const float*)d_in[6];
    const float* W_att    = (const float*)d_in[7];
    const float* conv_w   = (const float*)d_in[8];
    const float* w_w      = (const float*)d_in[9];
    const float* w_b      = (const float*)d_in[10];

    float* out_attc = (float*)d_out;                      // B*ENC
    float* out_attw = (float*)d_out + (size_t)B_ * ENC_;  // B*T

    k_decproj<<<B_, 256>>>(dec_st, W_dec, b_enc);
    {
        dim3 g(T_ / 128, B_);
        k_conv<<<g, 128>>>(prev, conv_w);
    }
    k_energy<<<B_ * (T_ / 64), 256>>>(enc, W_enc, W_att, w_w, w_b);
    k_softmax<<<B_, 256>>>(text_len, out_attw);
    {
        dim3 g(ENC_ / 256, NSPLIT_, B_);
        k_attc_part<<<g, 256>>>(enc, out_attw);
    }
    k_attc_reduce<<<(B_ * ENC_) / 256, 256>>>(out_attc);
}